// round 13
// baseline (speedup 1.0000x reference)
#include <cuda_runtime.h>
#include <cuda_bf16.h>

// MTCNN generate-boxes + greedy NMS, H=W=96, STRIDE=2, CELL=12, SCALE=0.6,
// THR_SCORE=0.6, THR_NMS=0.5.
//
// Exact structure exploited:
//   x1(c) = rintf(2c/0.6f) = nearest int to 10c/3;  x2 = x1 + 20 exactly
//   => all boxes are 21x21 (area 441), and IoU > 0.5  <=>  inter > 294 with
//      inter = (21-|dx1|)*(21-|dy1|). Suppression is therefore confined to the
//      12-neighbor stencil {(0,+-1),(0,+-2),(+-1,0),(+-2,0),(+-1,+-1)} with an
//      exact per-pair product check.
//
// Greedy NMS (priority = score desc, index asc) over a local stencil is the
// lexicographically-first maximal independent set: computed as a monotone
// fixpoint (UNKNOWN -> KEPT/DEAD) iterated inside one CTA.

#define HH 96
#define WW 96
#define NN (HH * WW)          // 9216
#define NTHREADS 1024
#define PER_THREAD (NN / NTHREADS)  // 9

__global__ void __launch_bounds__(NTHREADS, 1)
mtcnn_nms_kernel(const float* __restrict__ cls,
                 const float* __restrict__ reg,
                 float* __restrict__ out)
{
    __shared__ float         s_score[NN];   // 36864 B
    __shared__ unsigned char s_state[NN];   //  9216 B  (0=UNKNOWN 1=KEPT 2=DEAD)
    __shared__ int           s_x1[WW];      //   384 B  (same table for rows/cols)

    const int tid = threadIdx.x;

    if (tid < WW) {
        // matches jnp: round(STRIDE * c / SCALE) in float32, half-to-even
        s_x1[tid] = (int)rintf((2.0f * (float)tid) / 0.6f);
    }

#pragma unroll
    for (int k = 0; k < PER_THREAD; k++) {
        const int i = tid + k * NTHREADS;
        const float s = cls[i];
        s_score[i] = s;
        s_state[i] = (s > 0.6f) ? (unsigned char)0 : (unsigned char)2;
    }
    __syncthreads();

    // 12-neighbor stencil where suppression is geometrically possible
    const int drs[12] = { 0, 0, 0, 0, -1, 1, -2, 2, -1, -1,  1, 1};
    const int dcs[12] = {-1, 1, -2, 2,  0, 0,  0, 0, -1,  1, -1, 1};

    for (int round = 0; round < 4096; round++) {
        int myUnknown = 0;
#pragma unroll
        for (int k = 0; k < PER_THREAD; k++) {
            const int i = tid + k * NTHREADS;
            if (s_state[i] != 0) continue;
            const int r = i / WW, c = i % WW;
            const float si  = s_score[i];
            const int   x1i = s_x1[c];
            const int   y1i = s_x1[r];

            bool dead = false;
            bool allResolved = true;
#pragma unroll
            for (int nb = 0; nb < 12; nb++) {
                const int nr = r + drs[nb];
                const int nc = c + dcs[nb];
                if ((unsigned)nr >= HH || (unsigned)nc >= WW) continue;
                const int j = nr * WW + nc;
                const unsigned char stj = s_state[j];
                if (stj == 2) continue;                 // dead never suppresses
                const float sj = s_score[j];
                // j has higher priority than i? (score desc, then idx asc)
                const bool hp = (sj > si) || (sj == si && j < i);
                if (!hp) continue;
                // exact geometric overlap test: inter > 294  <=>  iou > 0.5
                const int wov = 21 - abs(x1i - s_x1[nc]);
                const int hov = 21 - abs(y1i - s_x1[nr]);
                if (wov * hov <= 294) continue;
                if (stj == 1) { dead = true; break; }   // kept neighbor suppresses i
                allResolved = false;                    // undecided higher-prio suppressor
            }
            if (dead)              s_state[i] = 2;
            else if (allResolved)  s_state[i] = 1;
            else                   myUnknown = 1;
        }
        if (__syncthreads_or(myUnknown) == 0) break;
    }

    // Output: boxes_c * keep, row layout [x1+r0*21, y1+r1*21, x2+r2*21, y2+r3*21, score]
#pragma unroll
    for (int k = 0; k < PER_THREAD; k++) {
        const int i = tid + k * NTHREADS;
        const int r = i / WW, c = i % WW;
        const float4 rg = reinterpret_cast<const float4*>(reg)[i];
        const float m  = (s_state[i] == 1) ? 1.0f : 0.0f;
        const float x1 = (float)s_x1[c];
        const float y1 = (float)s_x1[r];
        const float x2 = x1 + 20.0f;
        const float y2 = y1 + 20.0f;
        out[i * 5 + 0] = (x1 + rg.x * 21.0f) * m;
        out[i * 5 + 1] = (y1 + rg.y * 21.0f) * m;
        out[i * 5 + 2] = (x2 + rg.z * 21.0f) * m;
        out[i * 5 + 3] = (y2 + rg.w * 21.0f) * m;
        out[i * 5 + 4] = s_score[i] * m;
    }
}

extern "C" void kernel_launch(void* const* d_in, const int* in_sizes, int n_in,
                              void* d_out, int out_size)
{
    const float* cls = (const float*)d_in[0];   // cls_prob  [96,96]
    const float* reg = (const float*)d_in[1];   // bbox_pred [96,96,4]
    float* out = (float*)d_out;                 // [9216, 5]
    (void)in_sizes; (void)n_in; (void)out_size;
    mtcnn_nms_kernel<<<1, NTHREADS>>>(cls, reg, out);
}

// round 14
// speedup vs baseline: 2.5951x; 2.5951x over previous
#include <cuda_runtime.h>
#include <cuda_bf16.h>

// MTCNN generate-boxes + greedy NMS, H=W=96, STRIDE=2, CELL=12, SCALE=0.6,
// THR_SCORE=0.6, THR_NMS=0.5.
//
// All boxes are 21x21 (x2 = x1 + 20 exactly); IoU > 0.5 <=> inter > 294 with
// inter = (21-|dx1|)*(21-|dy1|). Suppression is confined to the 12-neighbor
// stencil {(0,+-1),(0,+-2),(+-1,0),(+-2,0),(+-1,+-1)} (validated in R12).
//
// Greedy NMS (priority = score desc, index asc) = lexicographically-first MIS
// of the static dominance DAG. This version precomputes the DAG as 12 per-
// offset dominance BITMAPS and runs the monotone fixpoint with bitwise ops:
// one thread per 32-bit word, funnel-shifted neighbor bitmaps, one barrier
// per round.

#define HH 96
#define WW 96
#define NN (HH * WW)      // 9216
#define PITCH 97          // score smem pitch (bank-conflict-free row stride)
#define NTH 1024
#define NWORDS 288        // 96 rows * 3 words

struct Smem {
    float    sc[HH * PITCH];     // 37248 B  padded scores
    unsigned dom[12 * NWORDS];   // 13824 B  per-offset dominance bitmaps
    unsigned u[2][NWORDS];       //  2304 B  UNKNOWN bitmaps (Jacobi double buf)
    unsigned k[NWORDS];          //  1152 B  KEPT bitmap (monotone, in-place)
    int      x1[WW];             //   384 B  x1 coordinate table
};

__global__ void __launch_bounds__(NTH, 1)
mtcnn_nms_kernel(const float* __restrict__ cls,
                 const float* __restrict__ reg,
                 float* __restrict__ out)
{
    extern __shared__ unsigned char smem_raw[];
    Smem* S = reinterpret_cast<Smem*>(smem_raw);
    const int tid = threadIdx.x;

    // coordinate table: matches jnp round(STRIDE*c/SCALE) in f32 (half-to-even)
    if (tid < WW) S->x1[tid] = (int)rintf((2.0f * (float)tid) / 0.6f);

    // load cls_prob into padded smem (float4 — rows are multiples of 4)
#pragma unroll
    for (int k4 = 0; k4 < 3; ++k4) {
        const int idx = tid + k4 * NTH;
        if (idx < NN / 4) {
            const float4 v = reinterpret_cast<const float4*>(cls)[idx];
            const int r = (4 * idx) / WW, c = (4 * idx) % WW;
            float* p = &S->sc[r * PITCH + c];
            p[0] = v.x; p[1] = v.y; p[2] = v.z; p[3] = v.w;
        }
    }
    __syncthreads();

    // ---- UNKNOWN init (valid = score > 0.6) + KEPT zero ----
    if (tid < NWORDS) {
        const int r = tid / 3, wi = tid % 3;
        const float* row = &S->sc[r * PITCH + wi * 32];
        unsigned u = 0;
#pragma unroll
        for (int b = 0; b < 32; ++b) u |= (row[b] > 0.6f) ? (1u << b) : 0u;
        S->u[0][tid] = u;
        S->k[tid] = 0u;
    }

    // ---- dominance bitmap precompute (static DAG) ----
    // offset o: neighbor at (r+DR[o], c+DC[o]); TW = tie-win (neighbor idx < mine)
    constexpr int DR[12] = { 0, 0, 0, 0,-1, 1,-2, 2,-1,-1, 1, 1};
    constexpr int DC[12] = {-1, 1,-2, 2, 0, 0, 0, 0,-1, 1,-1, 1};
    constexpr int TW[12] = { 1, 0, 1, 0, 1, 0, 1, 0, 1, 1, 0, 0};

    for (int w2 = tid; w2 < 12 * NWORDS; w2 += NTH) {
        const int r  = w2 % HH;          // row fastest -> conflict-free sc reads
        const int t2 = w2 / HH;
        const int wi = t2 % 3, o = t2 / 3;
        const int nr = r + DR[o];
        unsigned word = 0;
        if ((unsigned)nr < (unsigned)HH) {
            const int hov = 21 - abs(S->x1[r] - S->x1[nr]);
            const float* srow = &S->sc[r * PITCH];
            const float* nrow = &S->sc[nr * PITCH];
#pragma unroll
            for (int b = 0; b < 32; ++b) {
                const int c  = wi * 32 + b;
                const int nc = c + DC[o];
                if ((unsigned)nc >= (unsigned)WW) continue;
                const int wov = 21 - abs(S->x1[c] - S->x1[nc]);
                if (wov * hov <= 294) continue;          // exact IoU > 0.5 test
                const float si = srow[c], sj = nrow[nc];
                if (sj > si || (sj == si && TW[o])) word |= 1u << b;
            }
        }
        S->dom[o * NWORDS + r * 3 + wi] = word;
    }
    __syncthreads();

    // ---- bit-parallel fixpoint rounds ----
    const int w = tid, rr0 = tid / 3, wic = tid % 3;
    unsigned dreg[12];
    unsigned uown = 0;
    if (w < NWORDS) {
#pragma unroll
        for (int o = 0; o < 12; ++o) dreg[o] = S->dom[o * NWORDS + w];
        uown = S->u[0][w];
    }

    int cur = 0;
    for (int it = 0; it < 4096; ++it) {
        unsigned newU = 0;
        if (w < NWORDS) {
            unsigned acc[2];
#pragma unroll
            for (int pass = 0; pass < 2; ++pass) {
                const unsigned* src = pass ? S->u[cur] : S->k;
                unsigned mid[5], lov[5], hiv[5];
#pragma unroll
                for (int q = 0; q < 5; ++q) {
                    const int rq = rr0 - 2 + q;
                    const bool inb = (unsigned)rq < (unsigned)HH;
                    const int base = rq * 3 + wic;
                    mid[q] = inb ? src[base] : 0u;
                    lov[q] = (inb && wic > 0) ? src[base - 1] : 0u;
                    hiv[q] = (inb && wic < 2) ? src[base + 1] : 0u;
                }
                unsigned a = 0;
#pragma unroll
                for (int o = 0; o < 12; ++o) {
                    const int q = DR[o] + 2;
                    unsigned sh;
                    if (DC[o] == 0)       sh = mid[q];
                    else if (DC[o] == 1)  sh = __funnelshift_r(mid[q], hiv[q], 1);
                    else if (DC[o] == 2)  sh = __funnelshift_r(mid[q], hiv[q], 2);
                    else if (DC[o] == -1) sh = __funnelshift_l(lov[q], mid[q], 1);
                    else                  sh = __funnelshift_l(lov[q], mid[q], 2);
                    a |= sh & dreg[o];
                }
                acc[pass] = a;
            }
            const unsigned killed = acc[0], pend = acc[1];
            const unsigned kept = uown & ~killed & ~pend;
            if (kept) S->k[w] |= kept;        // owner-only write; monotone
            newU = uown & pend & ~killed;
            S->u[cur ^ 1][w] = newU;
            uown = newU;
        }
        if (__syncthreads_or((int)newU) == 0) break;
        cur ^= 1;
    }

    // ---- output: boxes_c * keep ----
#pragma unroll
    for (int kk = 0; kk < NN / NTH; ++kk) {
        const int i = tid + kk * NTH;
        const int r = i / WW, c = i % WW;
        const float4 rg = reinterpret_cast<const float4*>(reg)[i];
        const unsigned kw = S->k[r * 3 + (c >> 5)];
        const float m = ((kw >> (c & 31)) & 1u) ? 1.0f : 0.0f;
        const float x1 = (float)S->x1[c];
        const float y1 = (float)S->x1[r];
        out[i * 5 + 0] = (x1 + rg.x * 21.0f) * m;
        out[i * 5 + 1] = (y1 + rg.y * 21.0f) * m;
        out[i * 5 + 2] = (x1 + 20.0f + rg.z * 21.0f) * m;
        out[i * 5 + 3] = (y1 + 20.0f + rg.w * 21.0f) * m;
        out[i * 5 + 4] = S->sc[r * PITCH + c] * m;
    }
}

extern "C" void kernel_launch(void* const* d_in, const int* in_sizes, int n_in,
                              void* d_out, int out_size)
{
    const float* cls = (const float*)d_in[0];   // cls_prob  [96,96]
    const float* reg = (const float*)d_in[1];   // bbox_pred [96,96,4]
    float* out = (float*)d_out;                 // [9216, 5]
    (void)in_sizes; (void)n_in; (void)out_size;
    cudaFuncSetAttribute(mtcnn_nms_kernel,
                         cudaFuncAttributeMaxDynamicSharedMemorySize,
                         (int)sizeof(Smem));
    mtcnn_nms_kernel<<<1, NTH, sizeof(Smem)>>>(cls, reg, out);
}

// round 15
// speedup vs baseline: 5.5348x; 2.1327x over previous
#include <cuda_runtime.h>
#include <cuda_bf16.h>

// MTCNN generate-boxes + greedy NMS, H=W=96, STRIDE=2, CELL=12, SCALE=0.6,
// THR_SCORE=0.6, THR_NMS=0.5.
//
// Exact structure (validated R12/R13): x1(c)=round(10c/3)=(10c+1)/3, x2=x1+20,
// all boxes 21x21; IoU>0.5 <=> (21-|dx|)(21-|dy|) > 294; suppression confined
// to a 12-neighbor stencil whose overlap pattern is PERIOD-3 in r and c:
//   (0,+-1),(+-1,0): always overlap
//   (0,+2): only c%3==2   (0,-2): only c%3==1   (rows analogous)
//   (+1,+1): except r%3==1&&c%3==1   (+1,-1): except r%3==1&&c%3==2
//   (-1,-1): except r%3==2&&c%3==2   (-1,+1): except r%3==2&&c%3==1
//
// Priority (score desc, idx asc) is a strict total order => only 6 raw
// comparison bitmaps needed (ballot-built); opposite offsets are shifted
// complements. Greedy NMS = lex-first MIS of this static DAG, computed as a
// monotone fixpoint on (K=kept, A=alive) bitmaps. Both maps move one
// direction per bit and every observed transition is truth-based, so the
// iteration is correct under arbitrary interleaving -> multiple in-place
// sub-steps between barriers.

#define HH 96
#define WW 96
#define NN (HH * WW)
#define PITCH 97
#define NTH 384
#define NWORDS 288
#define SUBS 3

__device__ __forceinline__ uint2 lds_v2_vol(const uint2* p) {
    uint2 v;
    unsigned a = (unsigned)__cvta_generic_to_shared((void*)p);
    asm volatile("ld.volatile.shared.v2.u32 {%0,%1}, [%2];"
                 : "=r"(v.x), "=r"(v.y) : "r"(a));
    return v;
}
__device__ __forceinline__ void sts_v2_vol(uint2* p, unsigned x, unsigned y) {
    unsigned a = (unsigned)__cvta_generic_to_shared((void*)p);
    asm volatile("st.volatile.shared.v2.u32 [%0], {%1,%2};"
                 :: "r"(a), "r"(x), "r"(y) : "memory");
}

// bits b with (32*wi + b) % 3 == p
__device__ __forceinline__ unsigned colmask(int wi, int p) {
    const unsigned M[3] = {0x49249249u, 0x92492492u, 0x24924924u};
    return M[((p - 2 * wi) % 3 + 3) % 3];
}

__global__ void __launch_bounds__(NTH, 1)
mtcnn_nms_kernel(const float* __restrict__ cls,
                 const float* __restrict__ reg,
                 float* __restrict__ out)
{
    __shared__ float    sc[HH * PITCH];     // 37248 B padded scores
    __shared__ unsigned hpbm[6][NWORDS];    //  6912 B raw priority bitmaps
    __shared__ uint2    st[NWORDS];         //  2304 B (x=K kept, y=A alive)

    const int tid = threadIdx.x;

    // ---- load cls_prob into padded smem ----
#pragma unroll
    for (int k = 0; k < 6; ++k) {
        const int idx = tid + k * NTH;                 // 2304 float4
        const float4 v = reinterpret_cast<const float4*>(cls)[idx];
        const int rr = (4 * idx) / WW, cc = (4 * idx) % WW;
        float* p = &sc[rr * PITCH + cc];
        p[0] = v.x; p[1] = v.y; p[2] = v.z; p[3] = v.w;
    }
    __syncthreads();

    // ---- ballot phase: valid bitmap + 6 raw priority bitmaps ----
    // base offsets (all have positive linear index delta => tie loses):
    //   0:(0,+1) 1:(0,+2) 2:(+1,0) 3:(+2,0) 4:(+1,+1) 5:(+1,-1)
    {
        const int DRo[6] = {0, 0, 1, 2, 1, 1};
        const int DCo[6] = {1, 2, 0, 0, 1, -1};
#pragma unroll
        for (int k = 0; k < 24; ++k) {
            const int i = tid + k * NTH;               // warps align to words
            const int rr = i / WW, cc = i % WW;
            const float si = sc[rr * PITCH + cc];
            const unsigned vb = __ballot_sync(~0u, si > 0.6f);
            unsigned hp[6];
#pragma unroll
            for (int o = 0; o < 6; ++o) {
                int nr = rr + DRo[o]; nr = nr > 95 ? 95 : nr;
                int nc = cc + DCo[o]; nc = nc < 0 ? 0 : (nc > 95 ? 95 : nc);
                const float sj = sc[nr * PITCH + nc];
                hp[o] = __ballot_sync(~0u, sj > si);   // strict: tie -> lose
            }
            if ((i & 31) == 0) {
                const int w = i >> 5;
#pragma unroll
                for (int o = 0; o < 6; ++o) hpbm[o][w] = hp[o];
                st[w] = make_uint2(0u, vb);
            }
        }
    }
    __syncthreads();

    // ---- build 12 per-offset dominance words (registers, row-owner t<96) ----
    const int r = tid;
    unsigned dm[12][3];
    unsigned kk[3], aa[3];
    if (r < HH) {
        const int rp = r % 3;
#pragma unroll
        for (int wi = 0; wi < 3; ++wi) {
            const unsigned b_cge1  = (wi == 0) ? ~1u : ~0u;
            const unsigned b_cge2  = (wi == 0) ? ~3u : ~0u;
            const unsigned b_cle94 = (wi == 2) ? 0x7fffffffu : ~0u;
            const unsigned b_cle93 = (wi == 2) ? 0x3fffffffu : ~0u;
            const int base = r * 3 + wi;
            const unsigned h0 = hpbm[0][base], h1 = hpbm[1][base],
                           h2 = hpbm[2][base], h3 = hpbm[3][base],
                           h4 = hpbm[4][base], h5 = hpbm[5][base];
            // base offsets
            dm[0][wi] = h0 & b_cle94;                                   // (0,+1)
            dm[1][wi] = h1 & colmask(wi, 2) & b_cle93;                  // (0,+2)
            dm[2][wi] = (r <= 94) ? h2 : 0u;                            // (+1,0)
            dm[3][wi] = (rp == 2 && r <= 93) ? h3 : 0u;                 // (+2,0)
            dm[4][wi] = (r <= 94) ? (h4 & b_cle94 &
                          (rp == 1 ? ~colmask(wi, 1) : ~0u)) : 0u;      // (+1,+1)
            dm[5][wi] = (r <= 94) ? (h5 & b_cge1 &
                          (rp == 1 ? ~colmask(wi, 2) : ~0u)) : 0u;      // (+1,-1)
            // derived (shifted complements)
            {   // (0,-1): ~hp0[r] << 1
                const unsigned lo = (wi > 0) ? ~hpbm[0][base - 1] : 0u;
                dm[6][wi] = __funnelshift_l(lo, ~h0, 1) & b_cge1;
            }
            {   // (0,-2): ~hp1[r] << 2, ovl c%3==1
                const unsigned lo = (wi > 0) ? ~hpbm[1][base - 1] : 0u;
                dm[7][wi] = __funnelshift_l(lo, ~h1, 2) & colmask(wi, 1) & b_cge2;
            }
            dm[8][wi] = (r >= 1) ? ~hpbm[2][base - 3] : 0u;             // (-1,0)
            dm[9][wi] = (rp == 1 && r >= 2) ? ~hpbm[3][base - 6] : 0u;  // (-2,0)
            {   // (-1,-1): ~hp4[r-1] << 1, ovl !(r%3==2 && c%3==2)
                unsigned v = 0u;
                if (r >= 1) {
                    const unsigned lo = (wi > 0) ? ~hpbm[4][base - 4] : 0u;
                    v = __funnelshift_l(lo, ~hpbm[4][base - 3], 1) & b_cge1;
                    if (rp == 2) v &= ~colmask(wi, 2);
                }
                dm[10][wi] = v;
            }
            {   // (-1,+1): ~hp5[r-1] >> 1, ovl !(r%3==2 && c%3==1)
                unsigned v = 0u;
                if (r >= 1) {
                    const unsigned hi = (wi < 2) ? ~hpbm[5][base - 2] : 0u;
                    v = __funnelshift_r(~hpbm[5][base - 3], hi, 1) & b_cle94;
                    if (rp == 2) v &= ~colmask(wi, 1);
                }
                dm[11][wi] = v;
            }
        }
        kk[0] = 0u; kk[1] = 0u; kk[2] = 0u;
        aa[0] = st[r * 3 + 0].y; aa[1] = st[r * 3 + 1].y; aa[2] = st[r * 3 + 2].y;
    }

    // ---- asynchronous monotone fixpoint ----
    const int DR12[12] = {0, 0, 1, 2, 1, 1,  0,  0, -1, -2, -1, -1};
    const int DC12[12] = {1, 2, 0, 0, 1, -1, -1, -2, 0,  0,  -1, 1};

    for (int it = 0; it < 4096; ++it) {
        int ch = 0;
        if (r < HH) {
            const int rm2 = (r >= 2) ? r - 2 : 0;
            const int rm1 = (r >= 1) ? r - 1 : 0;
            const int rp1 = (r <= 94) ? r + 1 : 95;
            const int rp2 = (r <= 93) ? r + 2 : 95;
#pragma unroll
            for (int s = 0; s < SUBS; ++s) {
                unsigned RK[5][3], RA[5][3];
#pragma unroll
                for (int w = 0; w < 3; ++w) {
                    uint2 v0 = lds_v2_vol(&st[rm2 * 3 + w]);
                    uint2 v1 = lds_v2_vol(&st[rm1 * 3 + w]);
                    uint2 v3 = lds_v2_vol(&st[rp1 * 3 + w]);
                    uint2 v4 = lds_v2_vol(&st[rp2 * 3 + w]);
                    RK[0][w] = v0.x; RA[0][w] = v0.y;
                    RK[1][w] = v1.x; RA[1][w] = v1.y;
                    RK[3][w] = v3.x; RA[3][w] = v3.y;
                    RK[4][w] = v4.x; RA[4][w] = v4.y;
                    RK[2][w] = kk[w]; RA[2][w] = aa[w];
                }
#pragma unroll
                for (int wi = 0; wi < 3; ++wi) {
                    const unsigned U = aa[wi] & ~kk[wi];
                    unsigned pend = 0u, kill = 0u;
#pragma unroll
                    for (int o = 0; o < 12; ++o) {
                        const int q = DR12[o] + 2;
                        const int dc = DC12[o];
                        unsigned sA, sK;
                        if (dc == 0)      { sA = RA[q][wi]; sK = RK[q][wi]; }
                        else if (dc == 1) {
                            const unsigned hA = (wi < 2) ? RA[q][wi + 1] : 0u;
                            const unsigned hK = (wi < 2) ? RK[q][wi + 1] : 0u;
                            sA = __funnelshift_r(RA[q][wi], hA, 1);
                            sK = __funnelshift_r(RK[q][wi], hK, 1);
                        } else if (dc == 2) {
                            const unsigned hA = (wi < 2) ? RA[q][wi + 1] : 0u;
                            const unsigned hK = (wi < 2) ? RK[q][wi + 1] : 0u;
                            sA = __funnelshift_r(RA[q][wi], hA, 2);
                            sK = __funnelshift_r(RK[q][wi], hK, 2);
                        } else if (dc == -1) {
                            const unsigned lA = (wi > 0) ? RA[q][wi - 1] : 0u;
                            const unsigned lK = (wi > 0) ? RK[q][wi - 1] : 0u;
                            sA = __funnelshift_l(lA, RA[q][wi], 1);
                            sK = __funnelshift_l(lK, RK[q][wi], 1);
                        } else {
                            const unsigned lA = (wi > 0) ? RA[q][wi - 1] : 0u;
                            const unsigned lK = (wi > 0) ? RK[q][wi - 1] : 0u;
                            sA = __funnelshift_l(lA, RA[q][wi], 2);
                            sK = __funnelshift_l(lK, RK[q][wi], 2);
                        }
                        pend |= sA & dm[o][wi];
                        kill |= sK & dm[o][wi];
                    }
                    const unsigned kept   = U & ~pend;   // no dominating ALIVE
                    const unsigned killed = U & kill;    // dominating KEPT
                    if (kept | killed) {
                        kk[wi] |= kept;
                        aa[wi] &= ~killed;
                        ch = 1;
                    }
                }
                sts_v2_vol(&st[r * 3 + 0], kk[0], aa[0]);
                sts_v2_vol(&st[r * 3 + 1], kk[1], aa[1]);
                sts_v2_vol(&st[r * 3 + 2], kk[2], aa[2]);
            }
        }
        if (__syncthreads_or(ch) == 0) break;
    }

    // ---- output: boxes_c * keep ----
#pragma unroll
    for (int k = 0; k < 24; ++k) {
        const int i = tid + k * NTH;
        const int rr = i / WW, cc = i % WW;
        const float4 rg = reinterpret_cast<const float4*>(reg)[i];
        const unsigned kw = st[i >> 5].x;
        const float m = ((kw >> (i & 31)) & 1u) ? 1.0f : 0.0f;
        const float x1 = (float)((10 * cc + 1) / 3);
        const float y1 = (float)((10 * rr + 1) / 3);
        out[i * 5 + 0] = (x1 + rg.x * 21.0f) * m;
        out[i * 5 + 1] = (y1 + rg.y * 21.0f) * m;
        out[i * 5 + 2] = (x1 + 20.0f + rg.z * 21.0f) * m;
        out[i * 5 + 3] = (y1 + 20.0f + rg.w * 21.0f) * m;
        out[i * 5 + 4] = sc[rr * PITCH + cc] * m;
    }
}

extern "C" void kernel_launch(void* const* d_in, const int* in_sizes, int n_in,
                              void* d_out, int out_size)
{
    const float* cls = (const float*)d_in[0];   // cls_prob  [96,96]
    const float* reg = (const float*)d_in[1];   // bbox_pred [96,96,4]
    float* out = (float*)d_out;                 // [9216, 5]
    (void)in_sizes; (void)n_in; (void)out_size;
    mtcnn_nms_kernel<<<1, NTH>>>(cls, reg, out);
}

// round 16
// speedup vs baseline: 5.5913x; 1.0102x over previous
#include <cuda_runtime.h>
#include <cuda_bf16.h>

// MTCNN generate-boxes + greedy NMS, H=W=96, STRIDE=2, CELL=12, SCALE=0.6,
// THR_SCORE=0.6, THR_NMS=0.5.
//
// Exact structure (validated R12/R13): x1(c)=round(10c/3)=(10c+1)/3, x2=x1+20,
// all boxes 21x21; IoU>0.5 <=> (21-|dx|)(21-|dy|) > 294; suppression confined
// to a 12-neighbor stencil whose overlap pattern is PERIOD-3 in r and c:
//   (0,+-1),(+-1,0): always overlap
//   (0,+2): only c%3==2   (0,-2): only c%3==1   (rows analogous)
//   (+1,+1): except r%3==1&&c%3==1   (+1,-1): except r%3==1&&c%3==2
//   (-1,-1): except r%3==2&&c%3==2   (-1,+1): except r%3==2&&c%3==1
//
// Priority (score desc, idx asc) is a strict total order => only 6 raw
// comparison bitmaps needed (ballot-built); opposite offsets are shifted
// complements. Greedy NMS = lex-first MIS of this static DAG, computed as a
// monotone fixpoint on (K=kept, A=alive) bitmaps. Both maps move one
// direction per bit and every observed transition is truth-based, so the
// iteration is correct under arbitrary interleaving -> multiple in-place
// sub-steps between barriers.

#define HH 96
#define WW 96
#define NN (HH * WW)
#define PITCH 97
#define NTH 384
#define NWORDS 288
#define SUBS 3

__device__ __forceinline__ uint2 lds_v2_vol(const uint2* p) {
    uint2 v;
    unsigned a = (unsigned)__cvta_generic_to_shared((void*)p);
    asm volatile("ld.volatile.shared.v2.u32 {%0,%1}, [%2];"
                 : "=r"(v.x), "=r"(v.y) : "r"(a));
    return v;
}
__device__ __forceinline__ void sts_v2_vol(uint2* p, unsigned x, unsigned y) {
    unsigned a = (unsigned)__cvta_generic_to_shared((void*)p);
    asm volatile("st.volatile.shared.v2.u32 [%0], {%1,%2};"
                 :: "r"(a), "r"(x), "r"(y) : "memory");
}

// bits b with (32*wi + b) % 3 == p
__device__ __forceinline__ unsigned colmask(int wi, int p) {
    const unsigned M[3] = {0x49249249u, 0x92492492u, 0x24924924u};
    return M[((p - 2 * wi) % 3 + 3) % 3];
}

__global__ void __launch_bounds__(NTH, 1)
mtcnn_nms_kernel(const float* __restrict__ cls,
                 const float* __restrict__ reg,
                 float* __restrict__ out)
{
    __shared__ float    sc[HH * PITCH];     // 37248 B padded scores
    __shared__ unsigned hpbm[6][NWORDS];    //  6912 B raw priority bitmaps
    __shared__ uint2    st[NWORDS];         //  2304 B (x=K kept, y=A alive)

    const int tid = threadIdx.x;

    // ---- load cls_prob into padded smem ----
#pragma unroll
    for (int k = 0; k < 6; ++k) {
        const int idx = tid + k * NTH;                 // 2304 float4
        const float4 v = reinterpret_cast<const float4*>(cls)[idx];
        const int rr = (4 * idx) / WW, cc = (4 * idx) % WW;
        float* p = &sc[rr * PITCH + cc];
        p[0] = v.x; p[1] = v.y; p[2] = v.z; p[3] = v.w;
    }
    __syncthreads();

    // ---- ballot phase: valid bitmap + 6 raw priority bitmaps ----
    // base offsets (all have positive linear index delta => tie loses):
    //   0:(0,+1) 1:(0,+2) 2:(+1,0) 3:(+2,0) 4:(+1,+1) 5:(+1,-1)
    {
        const int DRo[6] = {0, 0, 1, 2, 1, 1};
        const int DCo[6] = {1, 2, 0, 0, 1, -1};
#pragma unroll
        for (int k = 0; k < 24; ++k) {
            const int i = tid + k * NTH;               // warps align to words
            const int rr = i / WW, cc = i % WW;
            const float si = sc[rr * PITCH + cc];
            const unsigned vb = __ballot_sync(~0u, si > 0.6f);
            unsigned hp[6];
#pragma unroll
            for (int o = 0; o < 6; ++o) {
                int nr = rr + DRo[o]; nr = nr > 95 ? 95 : nr;
                int nc = cc + DCo[o]; nc = nc < 0 ? 0 : (nc > 95 ? 95 : nc);
                const float sj = sc[nr * PITCH + nc];
                hp[o] = __ballot_sync(~0u, sj > si);   // strict: tie -> lose
            }
            if ((i & 31) == 0) {
                const int w = i >> 5;
#pragma unroll
                for (int o = 0; o < 6; ++o) hpbm[o][w] = hp[o];
                st[w] = make_uint2(0u, vb);
            }
        }
    }
    __syncthreads();

    // ---- build 12 per-offset dominance words (registers, row-owner t<96) ----
    const int r = tid;
    unsigned dm[12][3];
    unsigned kk[3], aa[3];
    if (r < HH) {
        const int rp = r % 3;
#pragma unroll
        for (int wi = 0; wi < 3; ++wi) {
            const unsigned b_cge1  = (wi == 0) ? ~1u : ~0u;
            const unsigned b_cge2  = (wi == 0) ? ~3u : ~0u;
            const unsigned b_cle94 = (wi == 2) ? 0x7fffffffu : ~0u;
            const unsigned b_cle93 = (wi == 2) ? 0x3fffffffu : ~0u;
            const int base = r * 3 + wi;
            const unsigned h0 = hpbm[0][base], h1 = hpbm[1][base],
                           h2 = hpbm[2][base], h3 = hpbm[3][base],
                           h4 = hpbm[4][base], h5 = hpbm[5][base];
            // base offsets
            dm[0][wi] = h0 & b_cle94;                                   // (0,+1)
            dm[1][wi] = h1 & colmask(wi, 2) & b_cle93;                  // (0,+2)
            dm[2][wi] = (r <= 94) ? h2 : 0u;                            // (+1,0)
            dm[3][wi] = (rp == 2 && r <= 93) ? h3 : 0u;                 // (+2,0)
            dm[4][wi] = (r <= 94) ? (h4 & b_cle94 &
                          (rp == 1 ? ~colmask(wi, 1) : ~0u)) : 0u;      // (+1,+1)
            dm[5][wi] = (r <= 94) ? (h5 & b_cge1 &
                          (rp == 1 ? ~colmask(wi, 2) : ~0u)) : 0u;      // (+1,-1)
            // derived (shifted complements)
            {   // (0,-1): ~hp0[r] << 1
                const unsigned lo = (wi > 0) ? ~hpbm[0][base - 1] : 0u;
                dm[6][wi] = __funnelshift_l(lo, ~h0, 1) & b_cge1;
            }
            {   // (0,-2): ~hp1[r] << 2, ovl c%3==1
                const unsigned lo = (wi > 0) ? ~hpbm[1][base - 1] : 0u;
                dm[7][wi] = __funnelshift_l(lo, ~h1, 2) & colmask(wi, 1) & b_cge2;
            }
            dm[8][wi] = (r >= 1) ? ~hpbm[2][base - 3] : 0u;             // (-1,0)
            dm[9][wi] = (rp == 1 && r >= 2) ? ~hpbm[3][base - 6] : 0u;  // (-2,0)
            {   // (-1,-1): ~hp4[r-1] << 1, ovl !(r%3==2 && c%3==2)
                unsigned v = 0u;
                if (r >= 1) {
                    const unsigned lo = (wi > 0) ? ~hpbm[4][base - 4] : 0u;
                    v = __funnelshift_l(lo, ~hpbm[4][base - 3], 1) & b_cge1;
                    if (rp == 2) v &= ~colmask(wi, 2);
                }
                dm[10][wi] = v;
            }
            {   // (-1,+1): ~hp5[r-1] >> 1, ovl !(r%3==2 && c%3==1)
                unsigned v = 0u;
                if (r >= 1) {
                    const unsigned hi = (wi < 2) ? ~hpbm[5][base - 2] : 0u;
                    v = __funnelshift_r(~hpbm[5][base - 3], hi, 1) & b_cle94;
                    if (rp == 2) v &= ~colmask(wi, 1);
                }
                dm[11][wi] = v;
            }
        }
        kk[0] = 0u; kk[1] = 0u; kk[2] = 0u;
        aa[0] = st[r * 3 + 0].y; aa[1] = st[r * 3 + 1].y; aa[2] = st[r * 3 + 2].y;
    }

    // ---- asynchronous monotone fixpoint ----
    const int DR12[12] = {0, 0, 1, 2, 1, 1,  0,  0, -1, -2, -1, -1};
    const int DC12[12] = {1, 2, 0, 0, 1, -1, -1, -2, 0,  0,  -1, 1};

    for (int it = 0; it < 4096; ++it) {
        int ch = 0;
        if (r < HH) {
            const int rm2 = (r >= 2) ? r - 2 : 0;
            const int rm1 = (r >= 1) ? r - 1 : 0;
            const int rp1 = (r <= 94) ? r + 1 : 95;
            const int rp2 = (r <= 93) ? r + 2 : 95;
#pragma unroll
            for (int s = 0; s < SUBS; ++s) {
                unsigned RK[5][3], RA[5][3];
#pragma unroll
                for (int w = 0; w < 3; ++w) {
                    uint2 v0 = lds_v2_vol(&st[rm2 * 3 + w]);
                    uint2 v1 = lds_v2_vol(&st[rm1 * 3 + w]);
                    uint2 v3 = lds_v2_vol(&st[rp1 * 3 + w]);
                    uint2 v4 = lds_v2_vol(&st[rp2 * 3 + w]);
                    RK[0][w] = v0.x; RA[0][w] = v0.y;
                    RK[1][w] = v1.x; RA[1][w] = v1.y;
                    RK[3][w] = v3.x; RA[3][w] = v3.y;
                    RK[4][w] = v4.x; RA[4][w] = v4.y;
                    RK[2][w] = kk[w]; RA[2][w] = aa[w];
                }
#pragma unroll
                for (int wi = 0; wi < 3; ++wi) {
                    const unsigned U = aa[wi] & ~kk[wi];
                    unsigned pend = 0u, kill = 0u;
#pragma unroll
                    for (int o = 0; o < 12; ++o) {
                        const int q = DR12[o] + 2;
                        const int dc = DC12[o];
                        unsigned sA, sK;
                        if (dc == 0)      { sA = RA[q][wi]; sK = RK[q][wi]; }
                        else if (dc == 1) {
                            const unsigned hA = (wi < 2) ? RA[q][wi + 1] : 0u;
                            const unsigned hK = (wi < 2) ? RK[q][wi + 1] : 0u;
                            sA = __funnelshift_r(RA[q][wi], hA, 1);
                            sK = __funnelshift_r(RK[q][wi], hK, 1);
                        } else if (dc == 2) {
                            const unsigned hA = (wi < 2) ? RA[q][wi + 1] : 0u;
                            const unsigned hK = (wi < 2) ? RK[q][wi + 1] : 0u;
                            sA = __funnelshift_r(RA[q][wi], hA, 2);
                            sK = __funnelshift_r(RK[q][wi], hK, 2);
                        } else if (dc == -1) {
                            const unsigned lA = (wi > 0) ? RA[q][wi - 1] : 0u;
                            const unsigned lK = (wi > 0) ? RK[q][wi - 1] : 0u;
                            sA = __funnelshift_l(lA, RA[q][wi], 1);
                            sK = __funnelshift_l(lK, RK[q][wi], 1);
                        } else {
                            const unsigned lA = (wi > 0) ? RA[q][wi - 1] : 0u;
                            const unsigned lK = (wi > 0) ? RK[q][wi - 1] : 0u;
                            sA = __funnelshift_l(lA, RA[q][wi], 2);
                            sK = __funnelshift_l(lK, RK[q][wi], 2);
                        }
                        pend |= sA & dm[o][wi];
                        kill |= sK & dm[o][wi];
                    }
                    const unsigned kept   = U & ~pend;   // no dominating ALIVE
                    const unsigned killed = U & kill;    // dominating KEPT
                    if (kept | killed) {
                        kk[wi] |= kept;
                        aa[wi] &= ~killed;
                        ch = 1;
                    }
                }
                sts_v2_vol(&st[r * 3 + 0], kk[0], aa[0]);
                sts_v2_vol(&st[r * 3 + 1], kk[1], aa[1]);
                sts_v2_vol(&st[r * 3 + 2], kk[2], aa[2]);
            }
        }
        if (__syncthreads_or(ch) == 0) break;
    }

    // ---- output: boxes_c * keep ----
#pragma unroll
    for (int k = 0; k < 24; ++k) {
        const int i = tid + k * NTH;
        const int rr = i / WW, cc = i % WW;
        const float4 rg = reinterpret_cast<const float4*>(reg)[i];
        const unsigned kw = st[i >> 5].x;
        const float m = ((kw >> (i & 31)) & 1u) ? 1.0f : 0.0f;
        const float x1 = (float)((10 * cc + 1) / 3);
        const float y1 = (float)((10 * rr + 1) / 3);
        out[i * 5 + 0] = (x1 + rg.x * 21.0f) * m;
        out[i * 5 + 1] = (y1 + rg.y * 21.0f) * m;
        out[i * 5 + 2] = (x1 + 20.0f + rg.z * 21.0f) * m;
        out[i * 5 + 3] = (y1 + 20.0f + rg.w * 21.0f) * m;
        out[i * 5 + 4] = sc[rr * PITCH + cc] * m;
    }
}

extern "C" void kernel_launch(void* const* d_in, const int* in_sizes, int n_in,
                              void* d_out, int out_size)
{
    const float* cls = (const float*)d_in[0];   // cls_prob  [96,96]
    const float* reg = (const float*)d_in[1];   // bbox_pred [96,96,4]
    float* out = (float*)d_out;                 // [9216, 5]
    (void)in_sizes; (void)n_in; (void)out_size;
    mtcnn_nms_kernel<<<1, NTH>>>(cls, reg, out);
}